// round 11
// baseline (speedup 1.0000x reference)
#include <cuda_runtime.h>

// AEV computer (ANI-style). B=8, A=48, S=4, NR=16, NA=4, NZ=8, npairs=10.
// Rcr=5.2, Rca=3.5. Output (8,48,384) f32.
// One CTA (256 threads) per (b,i) atom. Small-footprint pair staging (chunked
// for unconditional correctness) so multiple CTAs co-reside per SM.

#define B_   8
#define A_   48
#define S_   4
#define NR   16
#define NA   4
#define NZ   8
#define RAD  (S_*NR)       // 64
#define OUTL 384
#define RCR  5.2f
#define RCA  3.5f
#define PI_F 3.14159265358979323846f
#define NT   256
#define PCHUNK 256         // pair-staging chunk (real npair ~ 36; chunked loop
                           // keeps correctness for any m up to A_=48 -> 1128)

__global__ __launch_bounds__(NT) void aev_kernel(
    const int*   __restrict__ species,   // (B,A)
    const float* __restrict__ coords,    // (B,A,3)
    const float* __restrict__ gEtaR,     // (1)
    const float* __restrict__ gShfR,     // (16)
    const float* __restrict__ gEtaA,     // (1)
    const float* __restrict__ gZeta,     // (1)
    const float* __restrict__ gShfA,     // (4)
    const float* __restrict__ gShfZ,     // (8)
    float*       __restrict__ out)       // (B,A,384)
{
    __shared__ float sx[A_], sy[A_], sz[A_];
    __shared__ int   ssp[A_];
    __shared__ float vx[A_], vy[A_], vz[A_];
    __shared__ float sd[A_], sfca[A_], srw[A_];   // srw = 0.25*fc(Rcr) or 0
    __shared__ alignas(16) float acc[OUTL];
    __shared__ int   nbr[A_];
    __shared__ int   wcnt[2];
    __shared__ int   ncnt;
    __shared__ float shR[NR], shA[NA], cZ[NZ], sZ[NZ];
    __shared__ float cEtaR, cEtaA, cZeta;
    // per-pair staging, chunked
    __shared__ float pca[PCHUNK], psa[PCHUNK];
    __shared__ float pg[NA][PCHUNK];
    __shared__ int   pbase[PCHUNK];

    const int tid = threadIdx.x;
    const int bi  = blockIdx.x;            // b*A + i
    const int b   = bi / A_;
    const int i   = bi % A_;

    // ---- loads ----
    if (tid < A_) {
        int g = b * A_ + tid;
        sx[tid] = coords[g*3 + 0];
        sy[tid] = coords[g*3 + 1];
        sz[tid] = coords[g*3 + 2];
        ssp[tid] = species[g];
    }
    if (tid < NR) shR[tid] = gShfR[tid];
    if (tid < NA) shA[tid] = gShfA[tid];
    if (tid < NZ) { float v = gShfZ[tid]; cZ[tid] = cosf(v); sZ[tid] = sinf(v); }
    if (tid == 0) { cEtaR = gEtaR[0]; cEtaA = gEtaA[0]; cZeta = gZeta[0]; }
    for (int o = tid; o < OUTL; o += NT) acc[o] = 0.0f;
    __syncthreads();

    const int vi = (ssp[i] >= 0);

    // ---- Stage A: per-neighbor distances + cutoffs (2 warps), ballot compaction ----
    bool     inA = false;
    unsigned bal = 0;
    if (tid < 64) {
        const int j = tid;
        float fca = 0.0f;
        if (j < A_) {
            float dx = sx[i]-sx[j], dy = sy[i]-sy[j], dz = sz[i]-sz[j];
            float d  = sqrtf(dx*dx + dy*dy + dz*dz);
            if (j == i) d = 1.0f;
            vx[j]=dx; vy[j]=dy; vz[j]=dz; sd[j]=d;
            int pairok = vi && (ssp[j] >= 0) && (j != i);
            if (pairok && d <= RCA) fca = 0.5f*__cosf(d*(PI_F/RCA)) + 0.5f;
            sfca[j] = fca;
            srw[j]  = (pairok && d <= RCR) ? 0.25f*(0.5f*__cosf(d*(PI_F/RCR)) + 0.5f) : 0.0f;
        }
        inA = (fca > 0.0f);
        bal = __ballot_sync(0xFFFFFFFFu, inA);
        if ((tid & 31) == 0) wcnt[tid >> 5] = __popc(bal);
    }
    __syncthreads();
    if (inA) {
        int base = (tid >= 32) ? wcnt[0] : 0;
        nbr[base + __popc(bal & ((1u << (tid & 31)) - 1u))] = tid;
    }
    if (tid == 0) ncnt = wcnt[0] + wcnt[1];
    __syncthreads();

    const int   m     = ncnt;
    const int   npair = m * (m - 1) / 2;
    const float etaR  = cEtaR, etaA = cEtaA, zeta = cZeta;
    const bool  z32   = (zeta == 32.0f);

    // ---- Radial scatter over (j,r) items; item = j*16+r so each warp's
    //      atomics span two contiguous 16-wide blocks (<=2-way conflict) ----
    for (int it = tid; it < A_ * NR; it += NT) {
        const int j = it >> 4;
        const int r = it & (NR - 1);
        float w = srw[j];
        if (w != 0.0f) {
            float t = sd[j] - shR[r];
            atomicAdd(&acc[ssp[j]*NR + r], w * __expf(-etaR * t * t));
        }
    }

    // ---- Angular, chunked over unordered pairs (u<v). Ordered sum = 2x
    //      unordered; ref 2.0 * einsum 0.5 cancel -> weight 2.0. ----
    for (int p0 = 0; p0 < npair; p0 += PCHUNK) {
        const int pcnt = min(npair - p0, PCHUNK);

        // Stage B: z-invariant per-pair staging
        for (int pl = tid; pl < pcnt; pl += NT) {
            const int p = p0 + pl;
            int v = (int)((sqrtf(8.0f*(float)p + 1.0f) + 1.0f) * 0.5f);
            while (v*(v-1)/2 > p) v--;
            while ((v+1)*v/2 <= p) v++;
            int u = p - v*(v-1)/2;
            const int jj = nbr[u], kk = nbr[v];

            float dot = vx[jj]*vx[kk] + vy[jj]*vy[kk] + vz[jj]*vz[kk];
            float dd  = sd[jj] * sd[kk];
            float ca  = __fdividef(0.95f * dot, fmaxf(dd, 1e-8f));
            float sa  = sqrtf(fmaxf(1.0f - ca*ca, 0.0f));
            pca[pl] = ca; psa[pl] = sa;

            float wb = 2.0f * sfca[jj] * sfca[kk];
            float ds = 0.5f * (sd[jj] + sd[kk]);
            #pragma unroll
            for (int a = 0; a < NA; a++) {
                float t = ds - shA[a];
                pg[a][pl] = wb * __expf(-etaA * t * t);
            }

            int s1 = ssp[jj], s2 = ssp[kk];
            int lo = min(s1, s2), hi = max(s1, s2);
            int pidx = lo * (2*S_ - lo + 1) / 2 + (hi - lo);
            pbase[pl] = RAD + pidx * (NA*NZ);
        }
        __syncthreads();

        // Stage C: per (pair,z) item — exp-free squaring chain + 4 atomics
        const int items = pcnt * NZ;
        for (int it = tid; it < items; it += NT) {
            const int z  = it & (NZ - 1);
            const int pl = it >> 3;

            float cth = pca[pl] * cZ[z] + psa[pl] * sZ[z];   // cos(theta - ShfZ[z])
            float bv  = 0.5f * (1.0f + cth);
            float f1v;
            if (z32) { float t = bv*bv; t = t*t; t = t*t; t = t*t; f1v = t*t; }
            else      f1v = __powf(bv, zeta);

            int base = pbase[pl] + z;
            atomicAdd(&acc[base +  0], f1v * pg[0][pl]);
            atomicAdd(&acc[base +  8], f1v * pg[1][pl]);
            atomicAdd(&acc[base + 16], f1v * pg[2][pl]);
            atomicAdd(&acc[base + 24], f1v * pg[3][pl]);
        }
        __syncthreads();
    }

    if (npair == 0) __syncthreads();   // no-op path keeps nothing pending; acc already zeroed
    else { /* barriers already executed inside chunk loop */ }
    __syncthreads();

    // ---- write out: 384 floats = 96 float4 ----
    float4* op4 = reinterpret_cast<float4*>(out + (size_t)bi * OUTL);
    const float4* ac4 = reinterpret_cast<const float4*>(acc);
    for (int t = tid; t < OUTL/4; t += NT) op4[t] = ac4[t];
}

extern "C" void kernel_launch(void* const* d_in, const int* in_sizes, int n_in,
                              void* d_out, int out_size) {
    const int*   species = (const int*)  d_in[0];
    const float* coords  = (const float*)d_in[1];
    const float* EtaR    = (const float*)d_in[2];
    const float* ShfR    = (const float*)d_in[3];
    const float* EtaA    = (const float*)d_in[4];
    const float* Zeta    = (const float*)d_in[5];
    const float* ShfA    = (const float*)d_in[6];
    const float* ShfZ    = (const float*)d_in[7];
    float* out = (float*)d_out;
    (void)in_sizes; (void)n_in; (void)out_size;

    aev_kernel<<<B_ * A_, NT>>>(species, coords, EtaR, ShfR, EtaA, Zeta,
                                ShfA, ShfZ, out);
}

// round 15
// speedup vs baseline: 1.2177x; 1.2177x over previous
#include <cuda_runtime.h>

// AEV computer (ANI-style). B=8, A=48, S=4, NR=16, NA=4, NZ=8, npairs=10.
// Rcr=5.2, Rca=3.5. Output (8,48,384) f32.
// Role-split grid: CTA bid<384 computes the radial block (bins 0-63) of atom
// bid; CTA bid>=384 computes the angular block (bins 64-383) of atom bid-384.
// Disjoint output slices -> fully independent CTAs; 2x warps in flight.

#define B_   8
#define A_   48
#define S_   4
#define NR   16
#define NA   4
#define NZ   8
#define RAD  (S_*NR)       // 64
#define OUTL 384
#define RCR  5.2f
#define RCA  3.5f
#define PI_F 3.14159265358979323846f
#define NT   256
#define MAXP (A_*(A_-1)/2) // 1128 worst-case unordered pairs

__global__ __launch_bounds__(NT) void aev_kernel(
    const int*   __restrict__ species,   // (B,A)
    const float* __restrict__ coords,    // (B,A,3)
    const float* __restrict__ gEtaR,     // (1)
    const float* __restrict__ gShfR,     // (16)
    const float* __restrict__ gEtaA,     // (1)
    const float* __restrict__ gZeta,     // (1)
    const float* __restrict__ gShfA,     // (4)
    const float* __restrict__ gShfZ,     // (8)
    float*       __restrict__ out)       // (B,A,384)
{
    __shared__ float sx[A_], sy[A_], sz[A_];
    __shared__ int   ssp[A_];
    __shared__ float vx[A_], vy[A_], vz[A_];
    __shared__ float sd[A_], sfca[A_];
    __shared__ alignas(16) float acc[OUTL];
    __shared__ int   nbr[A_];
    __shared__ int   wcnt[2];
    __shared__ int   ncnt;
    __shared__ float shR[NR], shA[NA], cZ[NZ], sZ[NZ];
    __shared__ float cEtaR, cEtaA, cZeta;
    // per-pair staging (angular role only)
    __shared__ float pca[MAXP], psa[MAXP];
    __shared__ float pg[NA][MAXP];
    __shared__ int   pbase[MAXP];

    const int  tid     = threadIdx.x;
    const bool angular = (blockIdx.x >= B_ * A_);
    const int  bi      = angular ? (blockIdx.x - B_ * A_) : blockIdx.x;  // b*A + i
    const int  b       = bi / A_;
    const int  i       = bi % A_;

    // ---- loads ----
    if (tid < A_) {
        int g = b * A_ + tid;
        sx[tid] = coords[g*3 + 0];
        sy[tid] = coords[g*3 + 1];
        sz[tid] = coords[g*3 + 2];
        ssp[tid] = species[g];
    }
    if (tid < NR) shR[tid] = gShfR[tid];
    if (tid < NA) shA[tid] = gShfA[tid];
    if (tid < NZ) { float v = gShfZ[tid]; cZ[tid] = cosf(v); sZ[tid] = sinf(v); }
    if (tid == 0) { cEtaR = gEtaR[0]; cEtaA = gEtaA[0]; cZeta = gZeta[0]; }
    for (int o = tid; o < OUTL; o += NT) acc[o] = 0.0f;
    __syncthreads();

    const int vi = (ssp[i] >= 0);

    if (!angular) {
        // ================= RADIAL role: bins 0..63 =================
        if (tid < A_) {
            const int j = tid;
            float dx = sx[i]-sx[j], dy = sy[i]-sy[j], dz = sz[i]-sz[j];
            float d  = sqrtf(dx*dx + dy*dy + dz*dz);
            if (j == i) d = 1.0f;
            sd[j] = d;
            int pairok = vi && (ssp[j] >= 0) && (j != i);
            sfca[j] = (pairok && d <= RCR) ? 0.25f*(0.5f*__cosf(d*(PI_F/RCR)) + 0.5f)
                                          : 0.0f;   // reuse sfca as radial weight
        }
        __syncthreads();

        const float etaR = cEtaR;
        // scatter over (j,r) items; item = j*16+r: each warp's atomics span
        // two contiguous 16-wide blocks (<=2-way same-address conflict)
        for (int it = tid; it < A_ * NR; it += NT) {
            const int j = it >> 4;
            const int r = it & (NR - 1);
            float w = sfca[j];
            if (w != 0.0f) {
                float t = sd[j] - shR[r];
                atomicAdd(&acc[ssp[j]*NR + r], w * __expf(-etaR * t * t));
            }
        }
        __syncthreads();

        // write radial slice: 64 floats = 16 float4
        float4* op4 = reinterpret_cast<float4*>(out + (size_t)bi * OUTL);
        const float4* ac4 = reinterpret_cast<const float4*>(acc);
        if (tid < RAD/4) op4[tid] = ac4[tid];
        return;
    }

    // ================= ANGULAR role: bins 64..383 =================
    bool     inA = false;
    unsigned bal = 0;
    if (tid < 64) {
        const int j = tid;
        float fca = 0.0f;
        if (j < A_) {
            float dx = sx[i]-sx[j], dy = sy[i]-sy[j], dz = sz[i]-sz[j];
            float d  = sqrtf(dx*dx + dy*dy + dz*dz);
            if (j == i) d = 1.0f;
            vx[j]=dx; vy[j]=dy; vz[j]=dz; sd[j]=d;
            int pairok = vi && (ssp[j] >= 0) && (j != i);
            if (pairok && d <= RCA) fca = 0.5f*__cosf(d*(PI_F/RCA)) + 0.5f;
            sfca[j] = fca;
        }
        inA = (fca > 0.0f);
        bal = __ballot_sync(0xFFFFFFFFu, inA);
        if ((tid & 31) == 0) wcnt[tid >> 5] = __popc(bal);
    }
    __syncthreads();
    if (inA) {
        int base = (tid >= 32) ? wcnt[0] : 0;
        nbr[base + __popc(bal & ((1u << (tid & 31)) - 1u))] = tid;
    }
    if (tid == 0) ncnt = wcnt[0] + wcnt[1];
    __syncthreads();

    const int   m     = ncnt;
    const int   npair = m * (m - 1) / 2;
    const float etaA  = cEtaA, zeta = cZeta;
    const bool  z32   = (zeta == 32.0f);

    // Stage B: z-invariant per-pair staging (unordered pairs u<v).
    // Ordered sum = 2x unordered; ref 2.0 * einsum 0.5 cancel -> weight 2.0.
    for (int p = tid; p < npair; p += NT) {
        int v = (int)((sqrtf(8.0f*(float)p + 1.0f) + 1.0f) * 0.5f);
        while (v*(v-1)/2 > p) v--;
        while ((v+1)*v/2 <= p) v++;
        int u = p - v*(v-1)/2;
        const int jj = nbr[u], kk = nbr[v];

        float dot = vx[jj]*vx[kk] + vy[jj]*vy[kk] + vz[jj]*vz[kk];
        float dd  = sd[jj] * sd[kk];
        float ca  = __fdividef(0.95f * dot, fmaxf(dd, 1e-8f));
        float sa  = sqrtf(fmaxf(1.0f - ca*ca, 0.0f));
        pca[p] = ca; psa[p] = sa;

        float wb = 2.0f * sfca[jj] * sfca[kk];
        float ds = 0.5f * (sd[jj] + sd[kk]);
        #pragma unroll
        for (int a = 0; a < NA; a++) {
            float t = ds - shA[a];
            pg[a][p] = wb * __expf(-etaA * t * t);
        }

        int s1 = ssp[jj], s2 = ssp[kk];
        int lo = min(s1, s2), hi = max(s1, s2);
        int pidx = lo * (2*S_ - lo + 1) / 2 + (hi - lo);
        pbase[p] = RAD + pidx * (NA*NZ);
    }
    __syncthreads();

    // Stage C: per (pair,z) item — exp-free squaring chain + 4 atomics
    const int items = npair * NZ;
    for (int it = tid; it < items; it += NT) {
        const int z = it & (NZ - 1);
        const int p = it >> 3;

        float cth = pca[p] * cZ[z] + psa[p] * sZ[z];   // cos(theta - ShfZ[z])
        float bv  = 0.5f * (1.0f + cth);
        float f1v;
        if (z32) { float t = bv*bv; t = t*t; t = t*t; t = t*t; f1v = t*t; }
        else      f1v = __powf(bv, zeta);

        int base = pbase[p] + z;
        atomicAdd(&acc[base +  0], f1v * pg[0][p]);
        atomicAdd(&acc[base +  8], f1v * pg[1][p]);
        atomicAdd(&acc[base + 16], f1v * pg[2][p]);
        atomicAdd(&acc[base + 24], f1v * pg[3][p]);
    }
    __syncthreads();

    // write angular slice: 320 floats = 80 float4 (offset 64 floats = 16 float4)
    float4* op4 = reinterpret_cast<float4*>(out + (size_t)bi * OUTL);
    const float4* ac4 = reinterpret_cast<const float4*>(acc);
    for (int t = tid; t < (OUTL - RAD)/4; t += NT) op4[RAD/4 + t] = ac4[RAD/4 + t];
}

extern "C" void kernel_launch(void* const* d_in, const int* in_sizes, int n_in,
                              void* d_out, int out_size) {
    const int*   species = (const int*)  d_in[0];
    const float* coords  = (const float*)d_in[1];
    const float* EtaR    = (const float*)d_in[2];
    const float* ShfR    = (const float*)d_in[3];
    const float* EtaA    = (const float*)d_in[4];
    const float* Zeta    = (const float*)d_in[5];
    const float* ShfA    = (const float*)d_in[6];
    const float* ShfZ    = (const float*)d_in[7];
    float* out = (float*)d_out;
    (void)in_sizes; (void)n_in; (void)out_size;

    aev_kernel<<<2 * B_ * A_, NT>>>(species, coords, EtaR, ShfR, EtaA, Zeta,
                                    ShfA, ShfZ, out);
}